// round 3
// baseline (speedup 1.0000x reference)
#include <cuda_runtime.h>
#include <math.h>

// Problem constants
#define NT 16384   // B*T tokens
#define DD 1024    // embed dim
#define NE 8       // experts
#define HH 512     // bottleneck
#define TM 32      // token rows per expert-kernel block

// Scratch (static device arrays; no allocation allowed)
__device__ int   g_counts[NE];
__device__ int   g_tok [NE * NT];
__device__ float g_gate[NE * NT];

__global__ void zero_counts_kernel() {
    if (threadIdx.x < NE) g_counts[threadIdx.x] = 0;
}

// ---------------- Router: one warp per token ----------------
__global__ __launch_bounds__(256) void router_kernel(
    const float* __restrict__ x,
    const float* __restrict__ Wr, const float* __restrict__ br,
    const float* __restrict__ Wn, const float* __restrict__ bn,
    const float* __restrict__ noise)
{
    int warp = threadIdx.x >> 5;
    int lane = threadIdx.x & 31;
    int t = blockIdx.x * 8 + warp;
    if (t >= NT) return;

    const float* xr = x + (size_t)t * DD;
    float xv[32];
#pragma unroll
    for (int i = 0; i < 32; i++) xv[i] = xr[lane + 32 * i];

    float accR[NE], accN[NE];
#pragma unroll
    for (int e = 0; e < NE; e++) { accR[e] = 0.f; accN[e] = 0.f; }

#pragma unroll
    for (int i = 0; i < 32; i++) {
        int d = lane + 32 * i;
#pragma unroll
        for (int e = 0; e < NE; e++) {
            accR[e] += xv[i] * Wr[d * NE + e];
            accN[e] += xv[i] * Wn[d * NE + e];
        }
    }
#pragma unroll
    for (int e = 0; e < NE; e++) {
#pragma unroll
        for (int o = 16; o > 0; o >>= 1) {
            accR[e] += __shfl_xor_sync(0xFFFFFFFFu, accR[e], o);
            accN[e] += __shfl_xor_sync(0xFFFFFFFFu, accN[e], o);
        }
    }

    if (lane == 0) {
        float v[NE];
#pragma unroll
        for (int e = 0; e < NE; e++) {
            float z = accN[e] + bn[e];
            // numerically robust softplus: max(z,0) + log1p(exp(-|z|))
            float sp = fmaxf(z, 0.f) + log1pf(expf(-fabsf(z)));
            v[e] = accR[e] + br[e] + noise[(size_t)t * NE + e] * sp;
        }
        // top-2 (ties: lower index first, matching lax.top_k)
        int i0 = 0;
#pragma unroll
        for (int e = 1; e < NE; e++) if (v[e] > v[i0]) i0 = e;
        int i1 = (i0 == 0) ? 1 : 0;
#pragma unroll
        for (int e = 0; e < NE; e++) if (e != i0 && v[e] > v[i1]) i1 = e;

        float m  = fmaxf(v[i0], v[i1]);
        float g0 = expf(v[i0] - m);
        float g1 = expf(v[i1] - m);
        float inv = 1.f / (g0 + g1);
        g0 *= inv; g1 *= inv;

        int p0 = atomicAdd(&g_counts[i0], 1);
        g_tok[i0 * NT + p0] = t; g_gate[i0 * NT + p0] = g0;
        int p1 = atomicAdd(&g_counts[i1], 1);
        g_tok[i1 * NT + p1] = t; g_gate[i1 * NT + p1] = g1;
    }
}

// ---------------- Fused expert kernel ----------------
// grid = (NT/TM, NE), block = 256 threads. 8 warps; each warp owns 4 rows.
// smem: Xs[TM*DD] (128KB) + Hs[TM*HH] (64KB) = 192KB dynamic.
__global__ __launch_bounds__(256, 1) void expert_kernel(
    const float* __restrict__ x,
    const float* __restrict__ Wd, const float* __restrict__ bd,
    const float* __restrict__ Wu, const float* __restrict__ bu,
    float* __restrict__ out)
{
    extern __shared__ float smem[];
    float* Xs = smem;                // [TM][DD]
    float* Hs = smem + TM * DD;      // [TM][HH]
    __shared__ int   toks[TM];
    __shared__ float gates[TM];

    const int e    = blockIdx.y;
    const int tile = blockIdx.x;
    const int cnt  = g_counts[e];
    const int row0 = tile * TM;
    if (row0 >= cnt) return;
    const int nrows = min(TM, cnt - row0);

    const int tid = threadIdx.x;
    if (tid < TM) {
        if (tid < nrows) {
            toks[tid]  = g_tok [e * NT + row0 + tid];
            gates[tid] = g_gate[e * NT + row0 + tid];
        } else {                 // pad with row0's token, gate 0 (contributes nothing)
            toks[tid]  = g_tok[e * NT + row0];
            gates[tid] = 0.f;
        }
    }
    __syncthreads();

    // Load X tile (coalesced)
    for (int idx = tid; idx < TM * DD; idx += 256) {
        int r = idx >> 10;       // / DD
        int d = idx & (DD - 1);
        Xs[idx] = x[(size_t)toks[r] * DD + d];
    }
    __syncthreads();

    const int warpId = tid >> 5;
    const int lane   = tid & 31;
    const int r0     = warpId * 4;

    // ---- Down: [TM x HH] = Xs[TM x DD] * Wd[e] ----
    const float* WdE = Wd + (size_t)e * DD * HH;
    const float* bdE = bd + (size_t)e * HH;
#pragma unroll
    for (int cg = 0; cg < 4; cg++) {
        const int c0 = cg * 128 + lane;
        float acc[4][4];
#pragma unroll
        for (int r = 0; r < 4; r++)
#pragma unroll
            for (int j = 0; j < 4; j++) acc[r][j] = 0.f;

#pragma unroll 4
        for (int k = 0; k < DD; k++) {
            float wv0 = WdE[(size_t)k * HH + c0];
            float wv1 = WdE[(size_t)k * HH + c0 + 32];
            float wv2 = WdE[(size_t)k * HH + c0 + 64];
            float wv3 = WdE[(size_t)k * HH + c0 + 96];
            float x0 = Xs[(r0 + 0) * DD + k];
            float x1 = Xs[(r0 + 1) * DD + k];
            float x2 = Xs[(r0 + 2) * DD + k];
            float x3 = Xs[(r0 + 3) * DD + k];
            acc[0][0] += x0 * wv0; acc[0][1] += x0 * wv1; acc[0][2] += x0 * wv2; acc[0][3] += x0 * wv3;
            acc[1][0] += x1 * wv0; acc[1][1] += x1 * wv1; acc[1][2] += x1 * wv2; acc[1][3] += x1 * wv3;
            acc[2][0] += x2 * wv0; acc[2][1] += x2 * wv1; acc[2][2] += x2 * wv2; acc[2][3] += x2 * wv3;
            acc[3][0] += x3 * wv0; acc[3][1] += x3 * wv1; acc[3][2] += x3 * wv2; acc[3][3] += x3 * wv3;
        }
#pragma unroll
        for (int r = 0; r < 4; r++) {
#pragma unroll
            for (int j = 0; j < 4; j++) {
                int c = c0 + 32 * j;
                float v = acc[r][j] + bdE[c];
                // exact GELU: 0.5*v*(1+erf(v/sqrt(2)))
                float g = 0.5f * v * (1.f + erff(v * 0.70710678118654752440f));
                Hs[(r0 + r) * HH + c] = g;
            }
        }
    }
    __syncthreads();

    // ---- Up: [TM x DD] = Hs[TM x HH] * Wu[e]; gate-weighted atomic combine ----
    const float* WuE = Wu + (size_t)e * HH * DD;
    const float* buE = bu + (size_t)e * DD;
#pragma unroll
    for (int cg = 0; cg < 8; cg++) {
        const int c0 = cg * 128 + lane;
        float acc[4][4];
#pragma unroll
        for (int r = 0; r < 4; r++)
#pragma unroll
            for (int j = 0; j < 4; j++) acc[r][j] = 0.f;

#pragma unroll 4
        for (int k = 0; k < HH; k++) {
            float wv0 = WuE[(size_t)k * DD + c0];
            float wv1 = WuE[(size_t)k * DD + c0 + 32];
            float wv2 = WuE[(size_t)k * DD + c0 + 64];
            float wv3 = WuE[(size_t)k * DD + c0 + 96];
            float h0 = Hs[(r0 + 0) * HH + k];
            float h1 = Hs[(r0 + 1) * HH + k];
            float h2 = Hs[(r0 + 2) * HH + k];
            float h3 = Hs[(r0 + 3) * HH + k];
            acc[0][0] += h0 * wv0; acc[0][1] += h0 * wv1; acc[0][2] += h0 * wv2; acc[0][3] += h0 * wv3;
            acc[1][0] += h1 * wv0; acc[1][1] += h1 * wv1; acc[1][2] += h1 * wv2; acc[1][3] += h1 * wv3;
            acc[2][0] += h2 * wv0; acc[2][1] += h2 * wv1; acc[2][2] += h2 * wv2; acc[2][3] += h2 * wv3;
            acc[3][0] += h3 * wv0; acc[3][1] += h3 * wv1; acc[3][2] += h3 * wv2; acc[3][3] += h3 * wv3;
        }
#pragma unroll
        for (int r = 0; r < 4; r++) {
            float gt = gates[r0 + r];
            if (gt != 0.f) {
                size_t obase = (size_t)toks[r0 + r] * DD;
#pragma unroll
                for (int j = 0; j < 4; j++) {
                    int c = c0 + 32 * j;
                    atomicAdd(&out[obase + c], gt * (acc[r][j] + buE[c]));
                }
            }
        }
    }
}

extern "C" void kernel_launch(void* const* d_in, const int* in_sizes, int n_in,
                              void* d_out, int out_size)
{
    const float* x     = (const float*)d_in[0];
    const float* Wr    = (const float*)d_in[1];
    const float* br    = (const float*)d_in[2];
    const float* Wn    = (const float*)d_in[3];
    const float* bn    = (const float*)d_in[4];
    const float* Wd    = (const float*)d_in[5];
    const float* bd    = (const float*)d_in[6];
    const float* Wu    = (const float*)d_in[7];
    const float* bu    = (const float*)d_in[8];
    const float* noise = (const float*)d_in[9];
    float* out = (float*)d_out;

    static bool attr_done = false;
    if (!attr_done) {
        cudaFuncSetAttribute(expert_kernel,
                             cudaFuncAttributeMaxDynamicSharedMemorySize,
                             (TM * DD + TM * HH) * (int)sizeof(float));
        attr_done = true;
    }

    cudaMemsetAsync(d_out, 0, (size_t)out_size * sizeof(float), 0);
    zero_counts_kernel<<<1, 32, 0, 0>>>();
    router_kernel<<<NT / 8, 256, 0, 0>>>(x, Wr, br, Wn, bn, noise);

    dim3 grid(NT / TM, NE);
    size_t shmem = (size_t)(TM * DD + TM * HH) * sizeof(float);
    expert_kernel<<<grid, 256, shmem, 0>>>(x, Wd, bd, Wu, bu, out);
}

// round 8
// speedup vs baseline: 7.9276x; 7.9276x over previous
#include <cuda_runtime.h>
#include <cuda_bf16.h>
#include <math.h>
#include <stdint.h>

// ---------------- Problem constants ----------------
#define NT 16384   // B*T tokens
#define DD 1024    // embed dim
#define NE 8       // experts
#define HH 512     // bottleneck
#define TMR 128    // M tile per CTA
#define TN  128    // N tile per CTA
#define KCH 64     // K elems per smem stage (bf16 -> 128B rows, SW128)

#define TILE_B 16384                        // one (array,stage) tile: 128 rows x 128B
#define OFF_A 1024
#define OFF_B (OFF_A + 4 * TILE_B)
#define SMEM_TOTAL (OFF_B + 4 * TILE_B)     // 1024 + 128KB = 132096

// ---------------- Static device scratch ----------------
__device__ int   g_counts[NE];
__device__ int   g_offs[NE + 1];
__device__ int   g_tok [NE * NT];
__device__ float g_gate[NE * NT];
__device__ int   g_slot[NT * 2];

__device__ __nv_bfloat16 g_xhi[(size_t)NT * DD];
__device__ __nv_bfloat16 g_xlo[(size_t)NT * DD];
__device__ __nv_bfloat16 g_wdhi[(size_t)NE * HH * DD];  // WdT[e][h][d]
__device__ __nv_bfloat16 g_wdlo[(size_t)NE * HH * DD];
__device__ __nv_bfloat16 g_wuhi[(size_t)NE * DD * HH];  // WuT[e][d][h]
__device__ __nv_bfloat16 g_wulo[(size_t)NE * DD * HH];
__device__ __nv_bfloat16 g_Hhi[(size_t)(2 * NT + TMR) * HH];
__device__ __nv_bfloat16 g_Hlo[(size_t)(2 * NT + TMR) * HH];
__device__ float g_P[(size_t)(2 * NT + TMR) * DD];

// ---------------- Helpers ----------------
#define SWZ(o) ((o) ^ (((o) >> 3) & 0x70))

__device__ __forceinline__ uint32_t smem_u32(const void* p) {
    uint32_t a;
    asm("{ .reg .u64 t; cvta.to.shared.u64 t, %1; cvt.u32.u64 %0, t; }" : "=r"(a) : "l"(p));
    return a;
}
__device__ __forceinline__ void ldsm4(uint32_t* r, uint32_t a) {
    asm volatile("ldmatrix.sync.aligned.m8n8.x4.shared.b16 {%0,%1,%2,%3}, [%4];"
                 : "=r"(r[0]), "=r"(r[1]), "=r"(r[2]), "=r"(r[3]) : "r"(a));
}
__device__ __forceinline__ void mma_bf16(float* c, const uint32_t* a, const uint32_t* b) {
    asm volatile("mma.sync.aligned.m16n8k16.row.col.f32.bf16.bf16.f32 "
                 "{%0,%1,%2,%3}, {%4,%5,%6,%7}, {%8,%9}, {%0,%1,%2,%3};"
                 : "+f"(c[0]), "+f"(c[1]), "+f"(c[2]), "+f"(c[3])
                 : "r"(a[0]), "r"(a[1]), "r"(a[2]), "r"(a[3]), "r"(b[0]), "r"(b[1]));
}
__device__ __forceinline__ void split_bf(float v, __nv_bfloat16& h, __nv_bfloat16& l) {
    h = __float2bfloat16(v);
    l = __float2bfloat16(v - __bfloat162float(h));
}
__device__ __forceinline__ uint32_t pack2(__nv_bfloat16 a, __nv_bfloat16 b) {
    return (uint32_t)__bfloat16_as_ushort(a) | ((uint32_t)__bfloat16_as_ushort(b) << 16);
}

// ---------------- Aux kernels ----------------
__global__ void zero_counts_kernel() { if (threadIdx.x < NE) g_counts[threadIdx.x] = 0; }

__global__ void scan_kernel() {
    if (threadIdx.x == 0) {
        int a = 0;
        for (int e = 0; e < NE; e++) { g_offs[e] = a; a += g_counts[e]; }
        g_offs[NE] = a;
    }
}

__global__ __launch_bounds__(256) void conv_x_kernel(const float* __restrict__ x) {
    size_t i4 = ((size_t)blockIdx.x * 256 + threadIdx.x) * 4;
    float4 v = *(const float4*)(x + i4);
    __nv_bfloat16 h0,l0,h1,l1,h2,l2,h3,l3;
    split_bf(v.x,h0,l0); split_bf(v.y,h1,l1); split_bf(v.z,h2,l2); split_bf(v.w,h3,l3);
    ((uint2*)g_xhi)[i4 >> 2] = make_uint2(pack2(h0,h1), pack2(h2,h3));
    ((uint2*)g_xlo)[i4 >> 2] = make_uint2(pack2(l0,l1), pack2(l2,l3));
}

// WdT[e][n=h][k=d] = Wd[e][d][h]
__global__ __launch_bounds__(256) void conv_wd_kernel(const float* __restrict__ Wd) {
    size_t i4 = ((size_t)blockIdx.x * 256 + threadIdx.x) * 4;
    size_t e = i4 / ((size_t)HH * DD);
    size_t rem = i4 - e * (size_t)HH * DD;
    int n = (int)(rem / DD);
    int k = (int)(rem - (size_t)n * DD);
    __nv_bfloat16 h[4], l[4];
#pragma unroll
    for (int j = 0; j < 4; j++)
        split_bf(Wd[(e * DD + k + j) * HH + n], h[j], l[j]);
    ((uint2*)g_wdhi)[i4 >> 2] = make_uint2(pack2(h[0],h[1]), pack2(h[2],h[3]));
    ((uint2*)g_wdlo)[i4 >> 2] = make_uint2(pack2(l[0],l[1]), pack2(l[2],l[3]));
}

// WuT[e][n=d][k=h] = Wu[e][h][d]
__global__ __launch_bounds__(256) void conv_wu_kernel(const float* __restrict__ Wu) {
    size_t i4 = ((size_t)blockIdx.x * 256 + threadIdx.x) * 4;
    size_t e = i4 / ((size_t)DD * HH);
    size_t rem = i4 - e * (size_t)DD * HH;
    int n = (int)(rem / HH);
    int k = (int)(rem - (size_t)n * HH);
    __nv_bfloat16 h[4], l[4];
#pragma unroll
    for (int j = 0; j < 4; j++)
        split_bf(Wu[(e * HH + k + j) * DD + n], h[j], l[j]);
    ((uint2*)g_wuhi)[i4 >> 2] = make_uint2(pack2(h[0],h[1]), pack2(h[2],h[3]));
    ((uint2*)g_wulo)[i4 >> 2] = make_uint2(pack2(l[0],l[1]), pack2(l[2],l[3]));
}

// ---------------- Router ----------------
__global__ __launch_bounds__(256) void router_kernel(
    const float* __restrict__ x,
    const float* __restrict__ Wr, const float* __restrict__ br,
    const float* __restrict__ Wn, const float* __restrict__ bn,
    const float* __restrict__ noise)
{
    int warp = threadIdx.x >> 5;
    int lane = threadIdx.x & 31;
    int t = blockIdx.x * 8 + warp;
    if (t >= NT) return;

    const float* xr = x + (size_t)t * DD;
    float xv[32];
#pragma unroll
    for (int i = 0; i < 32; i++) xv[i] = xr[lane + 32 * i];

    float accR[NE], accN[NE];
#pragma unroll
    for (int e = 0; e < NE; e++) { accR[e] = 0.f; accN[e] = 0.f; }
#pragma unroll
    for (int i = 0; i < 32; i++) {
        int d = lane + 32 * i;
#pragma unroll
        for (int e = 0; e < NE; e++) {
            accR[e] += xv[i] * Wr[d * NE + e];
            accN[e] += xv[i] * Wn[d * NE + e];
        }
    }
#pragma unroll
    for (int e = 0; e < NE; e++) {
#pragma unroll
        for (int o = 16; o > 0; o >>= 1) {
            accR[e] += __shfl_xor_sync(0xFFFFFFFFu, accR[e], o);
            accN[e] += __shfl_xor_sync(0xFFFFFFFFu, accN[e], o);
        }
    }
    if (lane == 0) {
        float v[NE];
#pragma unroll
        for (int e = 0; e < NE; e++) {
            float z = accN[e] + bn[e];
            float sp = fmaxf(z, 0.f) + log1pf(expf(-fabsf(z)));
            v[e] = accR[e] + br[e] + noise[(size_t)t * NE + e] * sp;
        }
        int i0 = 0;
#pragma unroll
        for (int e = 1; e < NE; e++) if (v[e] > v[i0]) i0 = e;
        int i1 = (i0 == 0) ? 1 : 0;
#pragma unroll
        for (int e = 0; e < NE; e++) if (e != i0 && v[e] > v[i1]) i1 = e;

        float m  = fmaxf(v[i0], v[i1]);
        float g0 = expf(v[i0] - m);
        float g1 = expf(v[i1] - m);
        float inv = 1.f / (g0 + g1);
        g0 *= inv; g1 *= inv;

        int p0 = atomicAdd(&g_counts[i0], 1);
        g_tok[i0 * NT + p0] = t; g_gate[i0 * NT + p0] = g0;
        int p1 = atomicAdd(&g_counts[i1], 1);
        g_tok[i1 * NT + p1] = t; g_gate[i1 * NT + p1] = g1;
        g_slot[t * 2 + 0] = i0 * NT + p0;
        g_slot[t * 2 + 1] = i1 * NT + p1;
    }
}

// ---------------- HMMA GEMM (mode 0 = down+GELU, 1 = up+gate->P) ----------------
// 512 threads, 16 warps as 4(m) x 4(n); warp tile 32x32; split-bf16 3-pass.
__global__ __launch_bounds__(512, 1) void gemm_kernel(
    int mode, const float* __restrict__ bd, const float* __restrict__ bu)
{
    extern __shared__ char smem[];
    const int e = blockIdx.y, tile = blockIdx.x, zz = blockIdx.z;
    const int cnt = g_counts[e];
    if (tile * TMR >= cnt) return;
    const int nrows = min(TMR, cnt - tile * TMR);
    const int row_base = g_offs[e] + tile * TMR;

    const int tid = threadIdx.x;
    const int lane = tid & 31, wid = tid >> 5;
    const int wm = wid >> 2, wn = wid & 3;
    const int g = lane >> 2, t = lane & 3;
    const uint32_t sb = smem_u32(smem);

    __shared__ int   toks[TMR];
    __shared__ float gts [TMR];
    if (tid < TMR) {
        toks[tid] = (mode == 0 && tid < nrows) ? g_tok[e * NT + tile * TMR + tid] : 0;
        gts[tid]  = (mode == 1 && tid < nrows) ? g_gate[e * NT + tile * TMR + tid] : 0.f;
    }
    __syncthreads();

    const int S = (mode == 0) ? (DD / KCH) : (HH / KCH);   // 16 or 8
    const size_t ld = (mode == 0) ? DD : HH;               // row length for A and B sources

    // staging coords: 2 uint4 per array per thread (1024 uint4 per 16KB tile)
    const int r0 = tid >> 3, c0 = tid & 7, r1 = r0 + 64;
    const uint32_t dst0 = SWZ((uint32_t)(r0 * 128 + c0 * 16));
    const uint32_t dst1 = SWZ((uint32_t)(r1 * 128 + c0 * 16));

    const __nv_bfloat16 *Ah0, *Al0, *Ah1, *Al1;
    if (mode == 0) {
        Ah0 = g_xhi + (size_t)toks[r0] * DD;  Al0 = g_xlo + (size_t)toks[r0] * DD;
        Ah1 = g_xhi + (size_t)toks[r1] * DD;  Al1 = g_xlo + (size_t)toks[r1] * DD;
    } else {
        Ah0 = g_Hhi + (size_t)(row_base + r0) * HH;  Al0 = g_Hlo + (size_t)(row_base + r0) * HH;
        Ah1 = g_Hhi + (size_t)(row_base + r1) * HH;  Al1 = g_Hlo + (size_t)(row_base + r1) * HH;
    }
    const size_t bbase = (mode == 0) ? ((size_t)e * HH + (size_t)zz * TN) * DD
                                     : ((size_t)e * DD + (size_t)zz * TN) * HH;
    const __nv_bfloat16* Bhig = (mode == 0) ? g_wdhi : g_wuhi;
    const __nv_bfloat16* Blog = (mode == 0) ? g_wdlo : g_wulo;
    const __nv_bfloat16 *Bh0 = Bhig + bbase + (size_t)r0 * ld, *Bl0 = Blog + bbase + (size_t)r0 * ld;
    const __nv_bfloat16 *Bh1 = Bhig + bbase + (size_t)r1 * ld, *Bl1 = Blog + bbase + (size_t)r1 * ld;

    float acc[2][4][4];
#pragma unroll
    for (int mf = 0; mf < 2; mf++)
#pragma unroll
        for (int nf = 0; nf < 4; nf++)
#pragma unroll
            for (int q = 0; q < 4; q++) acc[mf][nf][q] = 0.f;

    // precomputed ldmatrix offsets (stage-independent)
    uint32_t offA[2][4], offB[2][4];
#pragma unroll
    for (int mf = 0; mf < 2; mf++) {
        int row = wm * 32 + mf * 16 + (lane & 7) + ((lane >> 3) & 1) * 8;
#pragma unroll
        for (int kk = 0; kk < 4; kk++)
            offA[mf][kk] = SWZ((uint32_t)(row * 128 + (kk * 2 + (lane >> 4)) * 16));
    }
#pragma unroll
    for (int pr = 0; pr < 2; pr++) {
        int nr = wn * 32 + pr * 16 + (lane >> 4) * 8 + (lane & 7);
#pragma unroll
        for (int kk = 0; kk < 4; kk++)
            offB[pr][kk] = SWZ((uint32_t)(nr * 128 + (kk * 2 + ((lane >> 3) & 1)) * 16));
    }

    auto compute_k16 = [&](uint32_t aH, uint32_t aL, uint32_t bH, uint32_t bL, int kk) {
        uint32_t ah[2][4], al[2][4], bh[4][2], bl[4][2];
#pragma unroll
        for (int mf = 0; mf < 2; mf++) {
            ldsm4(ah[mf], aH + offA[mf][kk]);
            ldsm4(al[mf], aL + offA[mf][kk]);
        }
#pragma unroll
        for (int pr = 0; pr < 2; pr++) {
            uint32_t q[4];
            // B stored [n][k] K-major: non-trans ldmatrix yields exact col-major
            // k-pair fragments (thread row index = n, register = consecutive k).
            ldsm4(q, bH + offB[pr][kk]);
            bh[pr*2][0]=q[0]; bh[pr*2][1]=q[1]; bh[pr*2+1][0]=q[2]; bh[pr*2+1][1]=q[3];
            ldsm4(q, bL + offB[pr][kk]);
            bl[pr*2][0]=q[0]; bl[pr*2][1]=q[1]; bl[pr*2+1][0]=q[2]; bl[pr*2+1][1]=q[3];
        }
#pragma unroll
        for (int mf = 0; mf < 2; mf++)
#pragma unroll
            for (int nf = 0; nf < 4; nf++) {
                mma_bf16(acc[mf][nf], ah[mf], bh[nf]);
                mma_bf16(acc[mf][nf], ah[mf], bl[nf]);
                mma_bf16(acc[mf][nf], al[mf], bh[nf]);
            }
    };

    // ---- prologue: stage 0 into buf 0 ----
    {
        *(uint4*)(smem + OFF_A + 0*TILE_B + dst0) = *(const uint4*)(Ah0 + c0*8);
        *(uint4*)(smem + OFF_A + 0*TILE_B + dst1) = *(const uint4*)(Ah1 + c0*8);
        *(uint4*)(smem + OFF_A + 1*TILE_B + dst0) = *(const uint4*)(Al0 + c0*8);
        *(uint4*)(smem + OFF_A + 1*TILE_B + dst1) = *(const uint4*)(Al1 + c0*8);
        *(uint4*)(smem + OFF_B + 0*TILE_B + dst0) = *(const uint4*)(Bh0 + c0*8);
        *(uint4*)(smem + OFF_B + 0*TILE_B + dst1) = *(const uint4*)(Bh1 + c0*8);
        *(uint4*)(smem + OFF_B + 1*TILE_B + dst0) = *(const uint4*)(Bl0 + c0*8);
        *(uint4*)(smem + OFF_B + 1*TILE_B + dst1) = *(const uint4*)(Bl1 + c0*8);
    }
    __syncthreads();

    int buf = 0;
    for (int s = 0; s < S; s++) {
        const uint32_t aH = sb + OFF_A + (buf*2+0)*TILE_B;
        const uint32_t aL = sb + OFF_A + (buf*2+1)*TILE_B;
        const uint32_t bH = sb + OFF_B + (buf*2+0)*TILE_B;
        const uint32_t bL = sb + OFF_B + (buf*2+1)*TILE_B;
        const bool pf = (s + 1 < S);
        const int kn = (s + 1) * KCH + c0 * 8;
        const int nb = buf ^ 1;

        uint4 nA0h, nA1h, nA0l, nA1l;
        if (pf) {
            nA0h = *(const uint4*)(Ah0 + kn);  nA1h = *(const uint4*)(Ah1 + kn);
            nA0l = *(const uint4*)(Al0 + kn);  nA1l = *(const uint4*)(Al1 + kn);
        }
        compute_k16(aH, aL, bH, bL, 0);
        compute_k16(aH, aL, bH, bL, 1);
        uint4 nB0h, nB1h, nB0l, nB1l;
        if (pf) {
            *(uint4*)(smem + OFF_A + (nb*2+0)*TILE_B + dst0) = nA0h;
            *(uint4*)(smem + OFF_A + (nb*2+0)*TILE_B + dst1) = nA1h;
            *(uint4*)(smem + OFF_A + (nb*2+1)*TILE_B + dst0) = nA0l;
            *(uint4*)(smem + OFF_A + (nb*2+1)*TILE_B + dst1) = nA1l;
            nB0h = *(const uint4*)(Bh0 + kn);  nB1h = *(const uint4*)(Bh1 + kn);
            nB0l = *(const uint4*)(Bl0 + kn);  nB1l = *(const uint4*)(Bl1 + kn);
        }
        compute_k16(aH, aL, bH, bL, 2);
        compute_k16(aH, aL, bH, bL, 3);
        if (pf) {
            *(uint4*)(smem + OFF_B + (nb*2+0)*TILE_B + dst0) = nB0h;
            *(uint4*)(smem + OFF_B + (nb*2+0)*TILE_B + dst1) = nB1h;
            *(uint4*)(smem + OFF_B + (nb*2+1)*TILE_B + dst0) = nB0l;
            *(uint4*)(smem + OFF_B + (nb*2+1)*TILE_B + dst1) = nB1l;
        }
        buf ^= 1;
        __syncthreads();
    }

    // ---- Epilogue ----
    if (mode == 0) {
#pragma unroll
        for (int nf = 0; nf < 4; nf++) {
            const int ncol = zz * TN + wn * 32 + nf * 8 + t * 2;
            const float b0 = bd[e * HH + ncol], b1 = bd[e * HH + ncol + 1];
#pragma unroll
            for (int mf = 0; mf < 2; mf++)
#pragma unroll
                for (int h = 0; h < 2; h++) {
                    const int row = wm * 32 + mf * 16 + g + h * 8;
                    if (row < nrows) {
                        float v0 = acc[mf][nf][h*2]     + b0;
                        float v1 = acc[mf][nf][h*2 + 1] + b1;
                        v0 = 0.5f * v0 * (1.f + erff(v0 * 0.70710678118654752440f));
                        v1 = 0.5f * v1 * (1.f + erff(v1 * 0.70710678118654752440f));
                        __nv_bfloat16 h0,l0,h1,l1;
                        split_bf(v0,h0,l0); split_bf(v1,h1,l1);
                        size_t base = (size_t)(row_base + row) * HH + ncol;
                        *(uint32_t*)(g_Hhi + base) = pack2(h0, h1);
                        *(uint32_t*)(g_Hlo + base) = pack2(l0, l1);
                    }
                }
        }
    } else {
#pragma unroll
        for (int nf = 0; nf < 4; nf++) {
            const int ncol = zz * TN + wn * 32 + nf * 8 + t * 2;
            const float b0 = bu[e * DD + ncol], b1 = bu[e * DD + ncol + 1];
#pragma unroll
            for (int mf = 0; mf < 2; mf++)
#pragma unroll
                for (int h = 0; h < 2; h++) {
                    const int row = wm * 32 + mf * 16 + g + h * 8;
                    if (row < nrows) {
                        const float gt = gts[row];
                        float2 o;
                        o.x = (acc[mf][nf][h*2]     + b0) * gt;
                        o.y = (acc[mf][nf][h*2 + 1] + b1) * gt;
                        *(float2*)(g_P + (size_t)(row_base + row) * DD + ncol) = o;
                    }
                }
        }
    }
}

// ---------------- Combine ----------------
__global__ __launch_bounds__(256) void combine_kernel(float* __restrict__ out) {
    const int t = blockIdx.x;
    const int c = threadIdx.x * 4;
    int vA = g_slot[2 * t], vB = g_slot[2 * t + 1];
    size_t rA = (size_t)g_offs[vA >> 14] + (vA & (NT - 1));
    size_t rB = (size_t)g_offs[vB >> 14] + (vB & (NT - 1));
    float4 a = *(const float4*)(g_P + rA * DD + c);
    float4 b = *(const float4*)(g_P + rB * DD + c);
    float4 o;
    o.x = a.x + b.x; o.y = a.y + b.y; o.z = a.z + b.z; o.w = a.w + b.w;
    *(float4*)(out + (size_t)t * DD + c) = o;
}

// ---------------- Launch ----------------
extern "C" void kernel_launch(void* const* d_in, const int* in_sizes, int n_in,
                              void* d_out, int out_size)
{
    const float* x     = (const float*)d_in[0];
    const float* Wr    = (const float*)d_in[1];
    const float* br    = (const float*)d_in[2];
    const float* Wn    = (const float*)d_in[3];
    const float* bn    = (const float*)d_in[4];
    const float* Wd    = (const float*)d_in[5];
    const float* bd    = (const float*)d_in[6];
    const float* Wu    = (const float*)d_in[7];
    const float* bu    = (const float*)d_in[8];
    const float* noise = (const float*)d_in[9];
    float* out = (float*)d_out;

    static bool attr_done = false;
    if (!attr_done) {
        cudaFuncSetAttribute(gemm_kernel,
                             cudaFuncAttributeMaxDynamicSharedMemorySize, SMEM_TOTAL);
        attr_done = true;
    }

    zero_counts_kernel<<<1, 32>>>();
    conv_x_kernel <<<(NT * DD) / 1024, 256>>>(x);
    conv_wd_kernel<<<(NE * HH * DD) / 1024, 256>>>(Wd);
    conv_wu_kernel<<<(NE * DD * HH) / 1024, 256>>>(Wu);
    router_kernel <<<NT / 8, 256>>>(x, Wr, br, Wn, bn, noise);
    scan_kernel   <<<1, 32>>>();

    gemm_kernel<<<dim3(NT / TMR, NE, 4), 512, SMEM_TOTAL>>>(0, bd, bu);  // down + GELU
    gemm_kernel<<<dim3(NT / TMR, NE, 8), 512, SMEM_TOTAL>>>(1, bd, bu);  // up + gate -> P
    combine_kernel<<<NT, 256>>>(out);
}

// round 13
// speedup vs baseline: 8.2345x; 1.0387x over previous
#include <cuda_runtime.h>
#include <cuda_bf16.h>
#include <math.h>
#include <stdint.h>

// ---------------- Problem constants ----------------
#define NT 16384   // B*T tokens
#define DD 1024    // embed dim
#define NE 8       // experts
#define HH 512     // bottleneck
#define TMR 128    // M tile per CTA
#define TN  128    // N tile per CTA
#define KCH 64     // K elems per smem stage (bf16 -> 128B rows, SW128)

#define TILE_B 16384                        // one (array,stage) tile: 128 rows x 128B
#define OFF_A 1024
#define OFF_B (OFF_A + 4 * TILE_B)
#define SMEM_TOTAL (OFF_B + 4 * TILE_B)     // 1024 + 128KB = 132096

// ---------------- Static device scratch ----------------
__device__ int   g_counts[NE];
__device__ int   g_offs[NE + 1];
__device__ int   g_tok [NE * NT];
__device__ float g_gate[NE * NT];
__device__ int   g_slot[NT * 2];

__device__ __nv_bfloat16 g_xhi[(size_t)NT * DD];
__device__ __nv_bfloat16 g_xlo[(size_t)NT * DD];
__device__ __nv_bfloat16 g_wdhi[(size_t)NE * HH * DD];  // WdT[e][h][d]
__device__ __nv_bfloat16 g_wdlo[(size_t)NE * HH * DD];
__device__ __nv_bfloat16 g_wuhi[(size_t)NE * DD * HH];  // WuT[e][d][h]
__device__ __nv_bfloat16 g_wulo[(size_t)NE * DD * HH];
__device__ __nv_bfloat16 g_Hhi[(size_t)(2 * NT + TMR) * HH];
__device__ __nv_bfloat16 g_Hlo[(size_t)(2 * NT + TMR) * HH];
__device__ float g_P[(size_t)(2 * NT + TMR) * DD];

// ---------------- Helpers ----------------
#define SWZ(o) ((o) ^ (((o) >> 3) & 0x70))

__device__ __forceinline__ uint32_t smem_u32(const void* p) {
    uint32_t a;
    asm("{ .reg .u64 t; cvta.to.shared.u64 t, %1; cvt.u32.u64 %0, t; }" : "=r"(a) : "l"(p));
    return a;
}
__device__ __forceinline__ void ldsm4(uint32_t* r, uint32_t a) {
    asm volatile("ldmatrix.sync.aligned.m8n8.x4.shared.b16 {%0,%1,%2,%3}, [%4];"
                 : "=r"(r[0]), "=r"(r[1]), "=r"(r[2]), "=r"(r[3]) : "r"(a));
}
__device__ __forceinline__ void mma_bf16(float* c, const uint32_t* a, const uint32_t* b) {
    asm volatile("mma.sync.aligned.m16n8k16.row.col.f32.bf16.bf16.f32 "
                 "{%0,%1,%2,%3}, {%4,%5,%6,%7}, {%8,%9}, {%0,%1,%2,%3};"
                 : "+f"(c[0]), "+f"(c[1]), "+f"(c[2]), "+f"(c[3])
                 : "r"(a[0]), "r"(a[1]), "r"(a[2]), "r"(a[3]), "r"(b[0]), "r"(b[1]));
}
__device__ __forceinline__ void cpa16(uint32_t dst, const void* src) {
    asm volatile("cp.async.cg.shared.global [%0], [%1], 16;" :: "r"(dst), "l"(src));
}
#define CPA_COMMIT() asm volatile("cp.async.commit_group;" ::: "memory")
#define CPA_WAIT0()  asm volatile("cp.async.wait_group 0;" ::: "memory")

__device__ __forceinline__ void split_bf(float v, __nv_bfloat16& h, __nv_bfloat16& l) {
    h = __float2bfloat16(v);
    l = __float2bfloat16(v - __bfloat162float(h));
}
__device__ __forceinline__ uint32_t pack2(__nv_bfloat16 a, __nv_bfloat16 b) {
    return (uint32_t)__bfloat16_as_ushort(a) | ((uint32_t)__bfloat16_as_ushort(b) << 16);
}

// ---------------- Aux kernels ----------------
__global__ void zero_counts_kernel() { if (threadIdx.x < NE) g_counts[threadIdx.x] = 0; }

__global__ void scan_kernel() {
    if (threadIdx.x == 0) {
        int a = 0;
        for (int e = 0; e < NE; e++) { g_offs[e] = a; a += g_counts[e]; }
        g_offs[NE] = a;
    }
}

__global__ __launch_bounds__(256) void conv_x_kernel(const float* __restrict__ x) {
    size_t i4 = ((size_t)blockIdx.x * 256 + threadIdx.x) * 4;
    float4 v = *(const float4*)(x + i4);
    __nv_bfloat16 h0,l0,h1,l1,h2,l2,h3,l3;
    split_bf(v.x,h0,l0); split_bf(v.y,h1,l1); split_bf(v.z,h2,l2); split_bf(v.w,h3,l3);
    ((uint2*)g_xhi)[i4 >> 2] = make_uint2(pack2(h0,h1), pack2(h2,h3));
    ((uint2*)g_xlo)[i4 >> 2] = make_uint2(pack2(l0,l1), pack2(l2,l3));
}

// WdT[e][n=h][k=d] = Wd[e][d][h]
__global__ __launch_bounds__(256) void conv_wd_kernel(const float* __restrict__ Wd) {
    size_t i4 = ((size_t)blockIdx.x * 256 + threadIdx.x) * 4;
    size_t e = i4 / ((size_t)HH * DD);
    size_t rem = i4 - e * (size_t)HH * DD;
    int n = (int)(rem / DD);
    int k = (int)(rem - (size_t)n * DD);
    __nv_bfloat16 h[4], l[4];
#pragma unroll
    for (int j = 0; j < 4; j++)
        split_bf(Wd[(e * DD + k + j) * HH + n], h[j], l[j]);
    ((uint2*)g_wdhi)[i4 >> 2] = make_uint2(pack2(h[0],h[1]), pack2(h[2],h[3]));
    ((uint2*)g_wdlo)[i4 >> 2] = make_uint2(pack2(l[0],l[1]), pack2(l[2],l[3]));
}

// WuT[e][n=d][k=h] = Wu[e][h][d]
__global__ __launch_bounds__(256) void conv_wu_kernel(const float* __restrict__ Wu) {
    size_t i4 = ((size_t)blockIdx.x * 256 + threadIdx.x) * 4;
    size_t e = i4 / ((size_t)DD * HH);
    size_t rem = i4 - e * (size_t)DD * HH;
    int n = (int)(rem / HH);
    int k = (int)(rem - (size_t)n * HH);
    __nv_bfloat16 h[4], l[4];
#pragma unroll
    for (int j = 0; j < 4; j++)
        split_bf(Wu[(e * HH + k + j) * DD + n], h[j], l[j]);
    ((uint2*)g_wuhi)[i4 >> 2] = make_uint2(pack2(h[0],h[1]), pack2(h[2],h[3]));
    ((uint2*)g_wulo)[i4 >> 2] = make_uint2(pack2(l[0],l[1]), pack2(l[2],l[3]));
}

// ---------------- Router ----------------
__global__ __launch_bounds__(256) void router_kernel(
    const float* __restrict__ x,
    const float* __restrict__ Wr, const float* __restrict__ br,
    const float* __restrict__ Wn, const float* __restrict__ bn,
    const float* __restrict__ noise)
{
    int warp = threadIdx.x >> 5;
    int lane = threadIdx.x & 31;
    int t = blockIdx.x * 8 + warp;
    if (t >= NT) return;

    const float* xr = x + (size_t)t * DD;
    float xv[32];
#pragma unroll
    for (int i = 0; i < 32; i++) xv[i] = xr[lane + 32 * i];

    float accR[NE], accN[NE];
#pragma unroll
    for (int e = 0; e < NE; e++) { accR[e] = 0.f; accN[e] = 0.f; }
#pragma unroll
    for (int i = 0; i < 32; i++) {
        int d = lane + 32 * i;
#pragma unroll
        for (int e = 0; e < NE; e++) {
            accR[e] += xv[i] * Wr[d * NE + e];
            accN[e] += xv[i] * Wn[d * NE + e];
        }
    }
#pragma unroll
    for (int e = 0; e < NE; e++) {
#pragma unroll
        for (int o = 16; o > 0; o >>= 1) {
            accR[e] += __shfl_xor_sync(0xFFFFFFFFu, accR[e], o);
            accN[e] += __shfl_xor_sync(0xFFFFFFFFu, accN[e], o);
        }
    }
    if (lane == 0) {
        float v[NE];
#pragma unroll
        for (int e = 0; e < NE; e++) {
            float z = accN[e] + bn[e];
            float sp = fmaxf(z, 0.f) + log1pf(expf(-fabsf(z)));
            v[e] = accR[e] + br[e] + noise[(size_t)t * NE + e] * sp;
        }
        int i0 = 0;
#pragma unroll
        for (int e = 1; e < NE; e++) if (v[e] > v[i0]) i0 = e;
        int i1 = (i0 == 0) ? 1 : 0;
#pragma unroll
        for (int e = 0; e < NE; e++) if (e != i0 && v[e] > v[i1]) i1 = e;

        float m  = fmaxf(v[i0], v[i1]);
        float g0 = expf(v[i0] - m);
        float g1 = expf(v[i1] - m);
        float inv = 1.f / (g0 + g1);
        g0 *= inv; g1 *= inv;

        int p0 = atomicAdd(&g_counts[i0], 1);
        g_tok[i0 * NT + p0] = t; g_gate[i0 * NT + p0] = g0;
        int p1 = atomicAdd(&g_counts[i1], 1);
        g_tok[i1 * NT + p1] = t; g_gate[i1 * NT + p1] = g1;
        g_slot[t * 2 + 0] = i0 * NT + p0;
        g_slot[t * 2 + 1] = i1 * NT + p1;
    }
}

// ---------------- HMMA GEMM (mode 0 = down+GELU, 1 = up+gate->P) ----------------
// 256 threads, 8 warps as 2(m) x 4(n); warp tile 64x32; split-bf16 3-pass;
// cp.async double-buffered pipeline.
__global__ __launch_bounds__(256, 1) void gemm_kernel(
    int mode, const float* __restrict__ bd, const float* __restrict__ bu)
{
    extern __shared__ char smem[];
    const int e = blockIdx.y, tile = blockIdx.x, zz = blockIdx.z;
    const int cnt = g_counts[e];
    if (tile * TMR >= cnt) return;
    const int nrows = min(TMR, cnt - tile * TMR);
    const int row_base = g_offs[e] + tile * TMR;

    const int tid = threadIdx.x;
    const int lane = tid & 31, wid = tid >> 5;
    const int wm = wid >> 2, wn = wid & 3;
    const int g = lane >> 2, t = lane & 3;
    const uint32_t sb = smem_u32(smem);

    __shared__ int   toks[TMR];
    __shared__ float gts [TMR];
    if (tid < TMR) {
        toks[tid] = (mode == 0 && tid < nrows) ? g_tok[e * NT + tile * TMR + tid] : 0;
        gts[tid]  = (mode == 1 && tid < nrows) ? g_gate[e * NT + tile * TMR + tid] : 0.f;
    }
    __syncthreads();

    const int S = (mode == 0) ? (DD / KCH) : (HH / KCH);   // 16 or 8
    const size_t ld = (mode == 0) ? DD : HH;               // row length of A and B sources

    // staging: 256 threads x 4 rows x 16B per 16KB tile array
    const int sr = tid >> 3, sc = tid & 7;   // sr 0..31, sc 0..7
    uint32_t sdst[4];
#pragma unroll
    for (int j = 0; j < 4; j++)
        sdst[j] = SWZ((uint32_t)((sr + 32 * j) * 128 + sc * 16));

    const size_t bbase = (mode == 0) ? ((size_t)e * HH + (size_t)zz * TN) * DD
                                     : ((size_t)e * DD + (size_t)zz * TN) * HH;
    const __nv_bfloat16* Bhig = (mode == 0) ? g_wdhi : g_wuhi;
    const __nv_bfloat16* Blog = (mode == 0) ? g_wdlo : g_wulo;

    const __nv_bfloat16 *pAh[4], *pAl[4], *pBh[4], *pBl[4];
#pragma unroll
    for (int j = 0; j < 4; j++) {
        const int r = sr + 32 * j;
        if (mode == 0) {
            pAh[j] = g_xhi + (size_t)toks[r] * DD + sc * 8;
            pAl[j] = g_xlo + (size_t)toks[r] * DD + sc * 8;
        } else {
            pAh[j] = g_Hhi + (size_t)(row_base + r) * HH + sc * 8;
            pAl[j] = g_Hlo + (size_t)(row_base + r) * HH + sc * 8;
        }
        pBh[j] = Bhig + bbase + (size_t)r * ld + sc * 8;
        pBl[j] = Blog + bbase + (size_t)r * ld + sc * 8;
    }

    float acc[4][4][4];
#pragma unroll
    for (int mf = 0; mf < 4; mf++)
#pragma unroll
        for (int nf = 0; nf < 4; nf++)
#pragma unroll
            for (int q = 0; q < 4; q++) acc[mf][nf][q] = 0.f;

    // ldmatrix offsets (stage-independent)
    uint32_t offA[4][4], offB[2][4];
#pragma unroll
    for (int mf = 0; mf < 4; mf++) {
        int row = wm * 64 + mf * 16 + (lane & 7) + ((lane >> 3) & 1) * 8;
#pragma unroll
        for (int kk = 0; kk < 4; kk++)
            offA[mf][kk] = SWZ((uint32_t)(row * 128 + (kk * 2 + (lane >> 4)) * 16));
    }
#pragma unroll
    for (int pr = 0; pr < 2; pr++) {
        int nr = wn * 32 + pr * 16 + (lane >> 4) * 8 + (lane & 7);
#pragma unroll
        for (int kk = 0; kk < 4; kk++)
            offB[pr][kk] = SWZ((uint32_t)(nr * 128 + (kk * 2 + ((lane >> 3) & 1)) * 16));
    }

    auto issue_stage = [&](int s, int b) {
        const int ko = s * KCH;
#pragma unroll
        for (int j = 0; j < 4; j++) {
            cpa16(sb + OFF_A + (b*2+0)*TILE_B + sdst[j], pAh[j] + ko);
            cpa16(sb + OFF_A + (b*2+1)*TILE_B + sdst[j], pAl[j] + ko);
            cpa16(sb + OFF_B + (b*2+0)*TILE_B + sdst[j], pBh[j] + ko);
            cpa16(sb + OFF_B + (b*2+1)*TILE_B + sdst[j], pBl[j] + ko);
        }
        CPA_COMMIT();
    };

    auto compute_k16 = [&](uint32_t aH, uint32_t aL, uint32_t bH, uint32_t bL, int kk) {
        uint32_t ah[4][4], al[4][4];
#pragma unroll
        for (int mf = 0; mf < 4; mf++) {
            ldsm4(ah[mf], aH + offA[mf][kk]);
            ldsm4(al[mf], aL + offA[mf][kk]);
        }
#pragma unroll
        for (int pr = 0; pr < 2; pr++) {
            uint32_t qh[4], ql[4];
            ldsm4(qh, bH + offB[pr][kk]);
            ldsm4(ql, bL + offB[pr][kk]);
#pragma unroll
            for (int half = 0; half < 2; half++) {
                const int nf = pr * 2 + half;
                const uint32_t bhf[2] = {qh[half*2], qh[half*2+1]};
                const uint32_t blf[2] = {ql[half*2], ql[half*2+1]};
#pragma unroll
                for (int mf = 0; mf < 4; mf++) {
                    mma_bf16(acc[mf][nf], ah[mf], bhf);
                    mma_bf16(acc[mf][nf], ah[mf], blf);
                    mma_bf16(acc[mf][nf], al[mf], bhf);
                }
            }
        }
    };

    // ---- prologue: stage 0 into buf 0 ----
    issue_stage(0, 0);
    CPA_WAIT0();
    __syncthreads();

    int buf = 0;
    for (int s = 0; s < S; s++) {
        const bool pf = (s + 1 < S);
        if (pf) issue_stage(s + 1, buf ^ 1);

        const uint32_t aH = sb + OFF_A + (buf*2+0)*TILE_B;
        const uint32_t aL = sb + OFF_A + (buf*2+1)*TILE_B;
        const uint32_t bH = sb + OFF_B + (buf*2+0)*TILE_B;
        const uint32_t bL = sb + OFF_B + (buf*2+1)*TILE_B;
        compute_k16(aH, aL, bH, bL, 0);
        compute_k16(aH, aL, bH, bL, 1);
        compute_k16(aH, aL, bH, bL, 2);
        compute_k16(aH, aL, bH, bL, 3);

        if (pf) CPA_WAIT0();
        __syncthreads();
        buf ^= 1;
    }

    // ---- Epilogue ----
    if (mode == 0) {
#pragma unroll
        for (int nf = 0; nf < 4; nf++) {
            const int ncol = zz * TN + wn * 32 + nf * 8 + t * 2;
            const float b0 = bd[e * HH + ncol], b1 = bd[e * HH + ncol + 1];
#pragma unroll
            for (int mf = 0; mf < 4; mf++)
#pragma unroll
                for (int h = 0; h < 2; h++) {
                    const int row = wm * 64 + mf * 16 + g + h * 8;
                    if (row < nrows) {
                        float v0 = acc[mf][nf][h*2]     + b0;
                        float v1 = acc[mf][nf][h*2 + 1] + b1;
                        v0 = 0.5f * v0 * (1.f + erff(v0 * 0.70710678118654752440f));
                        v1 = 0.5f * v1 * (1.f + erff(v1 * 0.70710678118654752440f));
                        __nv_bfloat16 h0,l0,h1,l1;
                        split_bf(v0,h0,l0); split_bf(v1,h1,l1);
                        size_t base = (size_t)(row_base + row) * HH + ncol;
                        *(uint32_t*)(g_Hhi + base) = pack2(h0, h1);
                        *(uint32_t*)(g_Hlo + base) = pack2(l0, l1);
                    }
                }
        }
    } else {
#pragma unroll
        for (int nf = 0; nf < 4; nf++) {
            const int ncol = zz * TN + wn * 32 + nf * 8 + t * 2;
            const float b0 = bu[e * DD + ncol], b1 = bu[e * DD + ncol + 1];
#pragma unroll
            for (int mf = 0; mf < 4; mf++)
#pragma unroll
                for (int h = 0; h < 2; h++) {
                    const int row = wm * 64 + mf * 16 + g + h * 8;
                    if (row < nrows) {
                        const float gt = gts[row];
                        float2 o;
                        o.x = (acc[mf][nf][h*2]     + b0) * gt;
                        o.y = (acc[mf][nf][h*2 + 1] + b1) * gt;
                        *(float2*)(g_P + (size_t)(row_base + row) * DD + ncol) = o;
                    }
                }
        }
    }
}

// ---------------- Combine ----------------
__global__ __launch_bounds__(256) void combine_kernel(float* __restrict__ out) {
    const int t = blockIdx.x;
    const int c = threadIdx.x * 4;
    int vA = g_slot[2 * t], vB = g_slot[2 * t + 1];
    size_t rA = (size_t)g_offs[vA >> 14] + (vA & (NT - 1));
    size_t rB = (size_t)g_offs[vB >> 14] + (vB & (NT - 1));
    float4 a = *(const float4*)(g_P + rA * DD + c);
    float4 b = *(const float4*)(g_P + rB * DD + c);
    float4 o;
    o.x = a.x + b.x; o.y = a.y + b.y; o.z = a.z + b.z; o.w = a.w + b.w;
    *(float4*)(out + (size_t)t * DD + c) = o;
}

// ---------------- Launch ----------------
extern "C" void kernel_launch(void* const* d_in, const int* in_sizes, int n_in,
                              void* d_out, int out_size)
{
    const float* x     = (const float*)d_in[0];
    const float* Wr    = (const float*)d_in[1];
    const float* br    = (const float*)d_in[2];
    const float* Wn    = (const float*)d_in[3];
    const float* bn    = (const float*)d_in[4];
    const float* Wd    = (const float*)d_in[5];
    const float* bd    = (const float*)d_in[6];
    const float* Wu    = (const float*)d_in[7];
    const float* bu    = (const float*)d_in[8];
    const float* noise = (const float*)d_in[9];
    float* out = (float*)d_out;

    static bool attr_done = false;
    if (!attr_done) {
        cudaFuncSetAttribute(gemm_kernel,
                             cudaFuncAttributeMaxDynamicSharedMemorySize, SMEM_TOTAL);
        attr_done = true;
    }

    zero_counts_kernel<<<1, 32>>>();
    conv_x_kernel <<<(NT * DD) / 1024, 256>>>(x);
    conv_wd_kernel<<<(NE * HH * DD) / 1024, 256>>>(Wd);
    conv_wu_kernel<<<(NE * DD * HH) / 1024, 256>>>(Wu);
    router_kernel <<<NT / 8, 256>>>(x, Wr, br, Wn, bn, noise);
    scan_kernel   <<<1, 32>>>();

    gemm_kernel<<<dim3(NT / TMR, NE, 4), 256, SMEM_TOTAL>>>(0, bd, bu);  // down + GELU
    gemm_kernel<<<dim3(NT / TMR, NE, 8), 256, SMEM_TOTAL>>>(1, bd, bu);  // up + gate -> P
    combine_kernel<<<NT, 256>>>(out);
}